// round 8
// baseline (speedup 1.0000x reference)
#include <cuda_runtime.h>

// Node2VecModel: N=6, EMB=32. One latency-bound kernel, warp-specialized:
//   warps 0-5 (bar 1): energy MLP -> out[0..5]
//   warp  6  (barrier-free): path logits + gumbel-max walk -> out[6..12]
// R8: fc2_w staged via float4 smem (384 scalar LDG instr -> 32 f4, staging
//     latency hidden behind prefetch+h1); path chain is one warp using
//     shuffle-based walk (no bar.sync, no smem); threefry baked at compile time.

#define NN   6
#define EMBD 32
#define H1   64
#define H2   32

// ---------------- compile-time threefry2x32 (partitionable JAX path) ----------------
struct TF2 { unsigned a, b; };

constexpr unsigned rotl_c(unsigned x, int r) { return (x << r) | (x >> (32 - r)); }

constexpr TF2 tf_const(unsigned k0, unsigned k1, unsigned x0, unsigned x1) {
    unsigned ks2 = k0 ^ k1 ^ 0x1BD11BDAu;
    x0 += k0; x1 += k1;
#define TFC(r) { x0 += x1; x1 = rotl_c(x1, r); x1 ^= x0; }
    TFC(13) TFC(15) TFC(26) TFC(6)
    x0 += k1;  x1 += ks2 + 1u;
    TFC(17) TFC(29) TFC(16) TFC(24)
    x0 += ks2; x1 += k0 + 2u;
    TFC(13) TFC(15) TFC(26) TFC(6)
    x0 += k0;  x1 += k1 + 3u;
    TFC(17) TFC(29) TFC(16) TFC(24)
    x0 += k1;  x1 += ks2 + 4u;
    TFC(13) TFC(15) TFC(26) TFC(6)
    x0 += ks2; x1 += k0 + 5u;
#undef TFC
    return TF2{x0, x1};
}

// split(key(42),5)[s] = tf((0,42),(0,s)); bits[j] = o0^o1 of tf(key,(0,j))
constexpr unsigned gbits(unsigned s, unsigned j) {
    TF2 key = tf_const(0u, 42u, 0u, s);
    TF2 o   = tf_const(key.a, key.b, 0u, j);
    return o.a ^ o.b;
}

#define GB(s) gbits(s,0), gbits(s,1), gbits(s,2), gbits(s,3), gbits(s,4), gbits(s,5)
__constant__ unsigned BITS[(NN - 1) * NN] = { GB(0), GB(1), GB(2), GB(3), GB(4) };
#undef GB

// JAX uniform(tiny,1) fp32 -> gumbel. (1-tiny) rounds to 1.0f => u = max(tiny, f+tiny).
__device__ __forceinline__ float gumbel_from_bits(unsigned b) {
    const float tiny = 1.1754943508222875e-38f;
    float f = __uint_as_float((b >> 9) | 0x3f800000u) - 1.0f;
    float u = fmaxf(__fadd_rn(f, tiny), tiny);
    return -logf(-logf(u));
}

#define BARSYNC(id, n) asm volatile("bar.sync %0, %1;" :: "r"(id), "r"(n) : "memory")

__global__ __launch_bounds__(224, 1)
void node2vec_kernel(const float* __restrict__ x,
                     const float* __restrict__ fc1_w, const float* __restrict__ fc1_b,
                     const float* __restrict__ fc2_w, const float* __restrict__ fc2_b,
                     const float* __restrict__ fc3_w, const float* __restrict__ fc3_b,
                     const float* __restrict__ pw,    const float* __restrict__ pb,
                     float* __restrict__ out) {
    __shared__ float sxE[NN * EMBD];
    __shared__ float h1s[NN][H1];
    __shared__ float w2s[H1 * H2];           // fc2_w staged as float4

    int tid = threadIdx.x;

    if (tid < 192) {
        // ================= ENERGY CHAIN (warps 0-5, bar.sync 1) =================
        int j1 = tid & 63, r1 = tid >> 6;          // h1 elems (r1,j1),(r1+3,j1)
        int i2 = tid >> 5, j2 = tid & 31;          // h2 elem (i2,j2); warp i2 = row i2

        // x first (feeds the barrier), then register-prefetch w1 (feeds h1),
        // then float4-stage w2 (only needed after the SECOND barrier).
        sxE[tid] = x[tid];

        float w1[EMBD];
        #pragma unroll
        for (int k = 0; k < EMBD; k++) w1[k] = fc1_w[k * H1 + j1];
        float b1v = fc1_b[j1];
        float b2v = fc2_b[j2];
        float w3v = fc3_w[j2];
        float b3v = fc3_b[0];

        {   // fc2_w = 512 float4; 192 threads, <=3 each. Latency hides behind h1.
            const float4* f2 = (const float4*)fc2_w;
            float4* d2 = (float4*)w2s;
            d2[tid] = f2[tid];
            d2[tid + 192] = f2[tid + 192];
            if (tid < 128) d2[tid + 384] = f2[tid + 384];
        }
        BARSYNC(1, 192);

        // h1 = relu(x @ fc1_w + b1): 2 rows per thread, independent accumulators
        {
            float a0 = b1v, a1 = b1v;
            #pragma unroll
            for (int k = 0; k < EMBD; k++) {
                a0 += sxE[r1 * EMBD + k]       * w1[k];
                a1 += sxE[(r1 + 3) * EMBD + k] * w1[k];
            }
            h1s[r1][j1]     = fmaxf(a0, 0.0f);
            h1s[r1 + 3][j1] = fmaxf(a1, 0.0f);
        }
        BARSYNC(1, 192);   // also drains the w2s STS

        // h2 + energy head fused: warp i2 owns row i2; lane j2 computes h2[i2][j2]
        // from smem w2 (bank = j2, conflict-free), scales by fc3_w[j2],
        // warp-reduces, lane 0 applies softplus and stores.
        {
            float c0 = 0.f, c1 = 0.f, c2 = 0.f, c3 = 0.f;
            #pragma unroll
            for (int k = 0; k < H1; k += 4) {
                c0 += h1s[i2][k]     * w2s[k * H2 + j2];
                c1 += h1s[i2][k + 1] * w2s[(k + 1) * H2 + j2];
                c2 += h1s[i2][k + 2] * w2s[(k + 2) * H2 + j2];
                c3 += h1s[i2][k + 3] * w2s[(k + 3) * H2 + j2];
            }
            float rel = fmaxf(b2v + ((c0 + c1) + (c2 + c3)), 0.0f);
            float p = rel * w3v;
            #pragma unroll
            for (int off = 16; off; off >>= 1)
                p += __shfl_xor_sync(0xffffffffu, p, off);
            if (j2 == 0) {
                float acc = p + b3v;
                out[i2] = fmaxf(acc, 0.0f) + log1pf(expf(-fabsf(acc)));  // softplus
            }
        }
    } else {
        // ============ PATH CHAIN (warp 6, barrier-free, smem-free) ============
        int l = tid - 192;                        // lane 0..31

        // logits idx l = (i,j) with i = l/6, j = l%6; lanes 0-3 also idx 32+l.
        int i0 = l / NN, j0 = l % NN;
        float acc0 = pb[j0];
        #pragma unroll
        for (int k = 0; k < EMBD; k++)
            acc0 += x[i0 * EMBD + k] * pw[k * NN + j0];

        float acc1 = 0.0f;                        // idx 32..35 -> row 5, j = l+2
        if (l < 4) {
            int j1p = l + 2;
            acc1 = pb[j1p];
            #pragma unroll
            for (int k = 0; k < EMBD; k++)
                acc1 += x[5 * EMBD + k] * pw[k * NN + j1p];
        }

        // one gumbel per lane (lanes 0-29): g for (step = l/6, j = l%6)
        float gv = 0.0f;
        if (l < (NN - 1) * NN) gv = gumbel_from_bits(BITS[l]);

        if (l == 0) { out[NN] = 0.0f; out[2 * NN] = 0.0f; }   // fixed endpoints

        // warp-converged gumbel-max walk; every lane runs identical scalar state.
        unsigned visited = 1u;                    // node 0 never revisited
        int cur = 0;
        #pragma unroll
        for (int step = 0; step < NN - 1; step++) {
            float best = -__int_as_float(0x7f800000);
            int bestj = 0;
            bool have = false;
            #pragma unroll
            for (int j = 0; j < NN; j++) {
                int idx = cur * NN + j;
                float lgA = __shfl_sync(0xffffffffu, acc0, idx & 31);
                float lgB = __shfl_sync(0xffffffffu, acc1, idx & 3);
                float lg = (idx < 32) ? lgA : lgB;
                float gg = __shfl_sync(0xffffffffu, gv, step * NN + j);  // imm lane
                float v = lg + gg;
                bool m = ((visited >> j) & 1u) == 0u;   // where(mask,.,-inf)+g
                if (m && (!have || v > best)) { best = v; bestj = j; have = true; }
            }
            visited |= 1u << bestj;
            cur = bestj;
            if (l == 0) out[NN + 1 + step] = (float)bestj;
        }
    }
}

extern "C" void kernel_launch(void* const* d_in, const int* in_sizes, int n_in,
                              void* d_out, int out_size) {
    const float* x     = (const float*)d_in[0];
    // d_in[1] = path (int32, unused by the forward outputs)
    const float* fc1_w = (const float*)d_in[2];
    const float* fc1_b = (const float*)d_in[3];
    const float* fc2_w = (const float*)d_in[4];
    const float* fc2_b = (const float*)d_in[5];
    const float* fc3_w = (const float*)d_in[6];
    const float* fc3_b = (const float*)d_in[7];
    const float* pw    = (const float*)d_in[8];
    const float* pb    = (const float*)d_in[9];
    float* out = (float*)d_out;

    node2vec_kernel<<<1, 224>>>(x, fc1_w, fc1_b, fc2_w, fc2_b,
                                fc3_w, fc3_b, pw, pb, out);
}

// round 9
// speedup vs baseline: 1.4010x; 1.4010x over previous
#include <cuda_runtime.h>

// Node2VecModel: N=6, EMB=32. One latency-bound kernel, warp-specialized:
//   warps 0-5 (bar 1): energy MLP -> out[0..5]
//   warps 6-8 (bar 2): raw path logits -> gumbel-max walk -> out[6..12]
// R9 = R7 (best measured) with the x LDG/STS issued FIRST so bar.sync 1
//      releases on the 1-line x load instead of draining the whole weight
//      prefetch burst (L1tex completion is issue-ordered).
// Invariants (measured): weights in REGISTERS (smem staging regressed 2x);
//      walk on thread 0 via smem (shuffle walk regressed); threefry baked
//      at compile time.

#define NN   6
#define EMBD 32
#define H1   64
#define H2   32

// ---------------- compile-time threefry2x32 (partitionable JAX path) ----------------
struct TF2 { unsigned a, b; };

constexpr unsigned rotl_c(unsigned x, int r) { return (x << r) | (x >> (32 - r)); }

constexpr TF2 tf_const(unsigned k0, unsigned k1, unsigned x0, unsigned x1) {
    unsigned ks2 = k0 ^ k1 ^ 0x1BD11BDAu;
    x0 += k0; x1 += k1;
#define TFC(r) { x0 += x1; x1 = rotl_c(x1, r); x1 ^= x0; }
    TFC(13) TFC(15) TFC(26) TFC(6)
    x0 += k1;  x1 += ks2 + 1u;
    TFC(17) TFC(29) TFC(16) TFC(24)
    x0 += ks2; x1 += k0 + 2u;
    TFC(13) TFC(15) TFC(26) TFC(6)
    x0 += k0;  x1 += k1 + 3u;
    TFC(17) TFC(29) TFC(16) TFC(24)
    x0 += k1;  x1 += ks2 + 4u;
    TFC(13) TFC(15) TFC(26) TFC(6)
    x0 += ks2; x1 += k0 + 5u;
#undef TFC
    return TF2{x0, x1};
}

// split(key(42),5)[s] = tf((0,42),(0,s)); bits[j] = o0^o1 of tf(key,(0,j))
constexpr unsigned gbits(unsigned s, unsigned j) {
    TF2 key = tf_const(0u, 42u, 0u, s);
    TF2 o   = tf_const(key.a, key.b, 0u, j);
    return o.a ^ o.b;
}

#define GB(s) gbits(s,0), gbits(s,1), gbits(s,2), gbits(s,3), gbits(s,4), gbits(s,5)
__constant__ unsigned BITS[(NN - 1) * NN] = { GB(0), GB(1), GB(2), GB(3), GB(4) };
#undef GB

// JAX uniform(tiny,1) fp32 -> gumbel. (1-tiny) rounds to 1.0f => u = max(tiny, f+tiny).
__device__ __forceinline__ float gumbel_from_bits(unsigned b) {
    const float tiny = 1.1754943508222875e-38f;
    float f = __uint_as_float((b >> 9) | 0x3f800000u) - 1.0f;
    float u = fmaxf(__fadd_rn(f, tiny), tiny);
    return -logf(-logf(u));
}

#define BARSYNC(id, n) asm volatile("bar.sync %0, %1;" :: "r"(id), "r"(n) : "memory")

__global__ __launch_bounds__(288, 1)
void node2vec_kernel(const float* __restrict__ x,
                     const float* __restrict__ fc1_w, const float* __restrict__ fc1_b,
                     const float* __restrict__ fc2_w, const float* __restrict__ fc2_b,
                     const float* __restrict__ fc3_w, const float* __restrict__ fc3_b,
                     const float* __restrict__ pw,    const float* __restrict__ pb,
                     float* __restrict__ out) {
    __shared__ float sxE[NN * EMBD];
    __shared__ float h1s[NN][H1];
    __shared__ float logits[NN][NN];         // raw logits (softmax cancels in argmax)
    __shared__ float g[NN - 1][NN];

    int tid = threadIdx.x;

    if (tid < 192) {
        // ================= ENERGY CHAIN (warps 0-5, bar.sync 1) =================
        int j1 = tid & 63, r1 = tid >> 6;          // h1 elems (r1,j1),(r1+3,j1)
        int i2 = tid >> 5, j2 = tid & 31;          // h2 elem (i2,j2); warp i2 = row i2

        // x FIRST: bar.sync 1 only protects sxE, and L1tex completes in issue
        // order — putting this LDG at the head of the queue releases the
        // barrier ~600cy earlier while the weight burst keeps streaming.
        sxE[tid] = x[tid];

        // register prefetch (issue-ordered: h1 deps before h2 deps)
        float w1[EMBD];
        #pragma unroll
        for (int k = 0; k < EMBD; k++) w1[k] = fc1_w[k * H1 + j1];
        float b1v = fc1_b[j1];

        float w2[H1];
        #pragma unroll
        for (int k = 0; k < H1; k++) w2[k] = fc2_w[k * H2 + j2];
        float b2v = fc2_b[j2];
        float w3v = fc3_w[j2];
        float b3v = fc3_b[0];

        BARSYNC(1, 192);

        // h1 = relu(x @ fc1_w + b1): 2 rows per thread, independent accumulators
        {
            float a0 = b1v, a1 = b1v;
            #pragma unroll
            for (int k = 0; k < EMBD; k++) {
                a0 += sxE[r1 * EMBD + k]       * w1[k];
                a1 += sxE[(r1 + 3) * EMBD + k] * w1[k];
            }
            h1s[r1][j1]     = fmaxf(a0, 0.0f);
            h1s[r1 + 3][j1] = fmaxf(a1, 0.0f);
        }
        BARSYNC(1, 192);

        // h2 + energy head fused: warp i2 owns row i2; lane j2 computes h2[i2][j2],
        // scales by fc3_w[j2], warp-reduces, lane 0 applies softplus and stores.
        {
            float c0 = 0.f, c1 = 0.f, c2 = 0.f, c3 = 0.f;
            #pragma unroll
            for (int k = 0; k < H1; k += 4) {
                c0 += h1s[i2][k]     * w2[k];
                c1 += h1s[i2][k + 1] * w2[k + 1];
                c2 += h1s[i2][k + 2] * w2[k + 2];
                c3 += h1s[i2][k + 3] * w2[k + 3];
            }
            float rel = fmaxf(b2v + ((c0 + c1) + (c2 + c3)), 0.0f);
            float p = rel * w3v;
            #pragma unroll
            for (int off = 16; off; off >>= 1)
                p += __shfl_xor_sync(0xffffffffu, p, off);
            if (j2 == 0) {
                float acc = p + b3v;
                out[i2] = fmaxf(acc, 0.0f) + log1pf(expf(-fabsf(acc)));  // softplus
            }
        }
    } else {
        // ================= PATH CHAIN (warps 6-8, bar.sync 2, 96 thr) =================
        int t = tid - 192;

        // fixed endpoints: write early from an otherwise-idle thread
        if (t == 40) { out[NN] = 0.0f; out[2 * NN] = 0.0f; }

        // raw logits = x @ path_fc_w + path_fc_b (36 threads) — LDG-bound,
        // issue first. log_softmax skipped: row constant cancels in the argmax.
        if (t < NN * NN) {
            int i = t / NN, j = t % NN;
            float acc = pb[j];
            #pragma unroll
            for (int k = 0; k < EMBD; k++)
                acc += x[i * EMBD + k] * pw[k * NN + j];
            logits[i][j] = acc;
        }

        // gumbels (warp 8, 30 threads): bits are compile-time constants; only
        // two device logf calls remain (bit-identical to the passing kernels).
        if (t >= 64 && t < 64 + (NN - 1) * NN) {
            int u = t - 64;
            g[u / NN][u % NN] = gumbel_from_bits(BITS[u]);
        }
        BARSYNC(2, 96);

        // serial gumbel-max walk (thread 192): 6 parallel LDS per step
        if (t == 0) {
            bool mask[NN];
            mask[0] = false;
            #pragma unroll
            for (int j = 1; j < NN; j++) mask[j] = true;

            int cur = 0;
            #pragma unroll
            for (int step = 0; step < NN - 1; step++) {
                float best = -__int_as_float(0x7f800000);
                int bestj = 0;
                bool have = false;
                #pragma unroll
                for (int j = 0; j < NN; j++) {
                    if (!mask[j]) continue;          // where(mask,.,-inf)+g = -inf
                    float v = logits[cur][j] + g[step][j];
                    if (!have || v > best) { best = v; bestj = j; have = true; }
                }
                cur = bestj;
                mask[bestj] = false;
                out[NN + 1 + step] = (float)bestj;
            }
        }
    }
}

extern "C" void kernel_launch(void* const* d_in, const int* in_sizes, int n_in,
                              void* d_out, int out_size) {
    const float* x     = (const float*)d_in[0];
    // d_in[1] = path (int32, unused by the forward outputs)
    const float* fc1_w = (const float*)d_in[2];
    const float* fc1_b = (const float*)d_in[3];
    const float* fc2_w = (const float*)d_in[4];
    const float* fc2_b = (const float*)d_in[5];
    const float* fc3_w = (const float*)d_in[6];
    const float* fc3_b = (const float*)d_in[7];
    const float* pw    = (const float*)d_in[8];
    const float* pb    = (const float*)d_in[9];
    float* out = (float*)d_out;

    node2vec_kernel<<<1, 288>>>(x, fc1_w, fc1_b, fc2_w, fc2_b,
                                fc3_w, fc3_b, pw, pb, out);
}